// round 12
// baseline (speedup 1.0000x reference)
#include <cuda_runtime.h>

#define Bn   8
#define Tn   1024
#define Cn   768
#define Hn   12
#define HIDn 1536
#define Mn   16
#define Pn   4
#define PREn 20
#define TAn  1044
#define SLICES 16
#define NSTG 3
#define STGF 2560            // floats per operand per stage
#define SMEM_BYTES (NSTG * STGF * 2 * 4)

// ---------------- scratch (device globals; no cudaMalloc allowed) ----------------
__device__ float g_q   [Bn*Tn*Cn];
__device__ float g_hbuf[Bn*Tn*HIDn];
__device__ float g_mem [Bn*Tn*Cn];
__device__ float g_pool[Bn*Mn*Cn];
__device__ float g_retr[Bn*Mn*Cn];
__device__ float g_xa  [Bn*TAn*Cn];
__device__ float g_hln [Bn*TAn*Cn];
__device__ float g_qkv [Bn*TAn*3*Cn];
__device__ float g_att [Bn*Hn*TAn*TAn];   // ~418MB
__device__ float g_y   [Bn*TAn*Cn];
__device__ float g_fc  [Bn*TAn*4*Cn];
__device__ float g_o   [Bn*Tn*Cn];
__device__ float g_key [Bn*Tn*Cn];
__device__ float g_val [Bn*Tn*Cn];
__device__ float g_pre [Bn*Tn*HIDn];
__device__ float g_hh  [Bn*Tn*HIDn];
__device__ float g_dpr [Bn*Tn*Cn];
__device__ float g_dhh [Bn*Tn*HIDn];
__device__ float g_p0  [SLICES*Bn*HIDn];
__device__ float g_p1  [SLICES*Bn*Cn];

// ---------------- generic strided batched GEMM params ----------------
struct GP {
    const float* A; const float* Bm; float* O; float* O2;
    const float* bias; const float* aux; const float* aux2;
    int M, N, K, binner;
    long long sAm, sAk, bA, bA2;
    long long sBk, sBn, bB, bB2;
    long long sOm, sOn, bO, bO2;
    long long bBias;
    int mode, prefix, tri;
    float scale;
};
// modes: 0=bias 1=silu(+pre->O2) 2=gelu 3=attn scale+mask 4=residual-add
//        5=dpred 6=silu-bwd(aux=pre) 7=momentum update (aux=mem, aux2=mom, O=nw, O2=nmom)
// tri: 1=skip fully-masked blocks (scores), 2=cap K at m0+128 (attn y)

__device__ __forceinline__ unsigned f2tf(float x) {
    unsigned r;
    asm("cvt.rna.tf32.f32 %0, %1;" : "=r"(r) : "f"(x));
    return r;
}

__device__ __forceinline__ void mma_tf32(float* c, const unsigned* a, const unsigned* b) {
    asm volatile(
        "mma.sync.aligned.m16n8k8.row.col.f32.tf32.tf32.f32 "
        "{%0,%1,%2,%3}, {%4,%5,%6,%7}, {%8,%9}, {%0,%1,%2,%3};\n"
        : "+f"(c[0]), "+f"(c[1]), "+f"(c[2]), "+f"(c[3])
        : "r"(a[0]), "r"(a[1]), "r"(a[2]), "r"(a[3]), "r"(b[0]), "r"(b[1]));
}

__device__ __forceinline__ void cp16(float* dst, const float* src, bool pred) {
    unsigned d = (unsigned)__cvta_generic_to_shared(dst);
    int sz = pred ? 16 : 0;
    asm volatile("cp.async.cg.shared.global [%0], [%1], 16, %2;\n"
                 :: "r"(d), "l"(src), "r"(sz));
}
#define CP_COMMIT() asm volatile("cp.async.commit_group;\n" ::)

__device__ __forceinline__ void epi_write(const GP& p, int m, int n, float v,
                                          long long offO, long long offBias) {
    if (m >= p.M || n >= p.N) return;
    long long o = offO + (long long)m * p.sOm + (long long)n * p.sOn;
    float bsv = p.bias ? p.bias[offBias + n] : 0.f;
    switch (p.mode) {
        case 0: p.O[o] = v + bsv; break;
        case 1: { float z = v + bsv; if (p.O2) p.O2[o] = z;
                  float sg = 1.f / (1.f + __expf(-z)); p.O[o] = z * sg; } break;
        case 2: { float z = v + bsv; p.O[o] = 0.5f * z * (1.f + erff(z * 0.70710678118f)); } break;
        case 3: { float z = v * p.scale; if (m >= p.prefix && n > m) z = -1e30f; p.O[o] = z; } break;
        case 4: p.O[o] = p.aux[o] + v + bsv; break;
        case 5: p.O[o] = (v + bsv - p.aux[o]) * p.scale; break;
        case 6: { float z = p.aux[o]; float sg = 1.f / (1.f + __expf(-z));
                  p.O[o] = v * sg * (1.f + z * (1.f - sg)); } break;
        case 7: { float nm = 0.9f * p.aux2[o] + v; p.O2[o] = nm;
                  p.O[o] = 0.999f * p.aux[o] - 0.01f * nm; } break;
    }
}

// ---- tf32 tensor-core GEMM: 128x128 block, k-tile 16, 8 warps ----
// cp.async GMEM->SMEM, 3-stage ring (wait_group 1), ONE sync per k-iter,
// 32 MMAs per iter. Orientation-matched smem layouts, conflict-free frag LDS:
//   k-contiguous operand : row layout [128][20]
//   m/n-contiguous       : col layout [16][132]
__global__ void __launch_bounds__(256, 2) gemm_tc(GP p) {
    extern __shared__ float smem[];
    float* sA = smem;                    // NSTG * STGF
    float* sB = smem + NSTG * STGF;      // NSTG * STGF
    int bz = blockIdx.z;
    int bo = bz / p.binner, bi = bz % p.binner;
    const float* Ap = p.A  + (long long)bo * p.bA + (long long)bi * p.bA2;
    const float* Bp = p.Bm + (long long)bo * p.bB + (long long)bi * p.bB2;
    int m0 = blockIdx.y * 128, n0 = blockIdx.x * 128;

    // triangular-mask shortcuts
    if (p.tri == 1 && m0 > 0 && n0 >= m0 + 128) return;
    int Keff = p.K;
    if (p.tri == 2 && m0 > 0 && m0 + 128 < Keff) Keff = m0 + 128;

    int tid = threadIdx.x;
    int warp = tid >> 5, lane = tid & 31;
    int wm = warp & 1, wn = warp >> 1;      // warp tile: 64 (m) x 32 (n)
    int lq = lane >> 2, lr = lane & 3;

    float acc[4][4][4];
#pragma unroll
    for (int i = 0; i < 4; i++)
#pragma unroll
        for (int j = 0; j < 4; j++)
#pragma unroll
            for (int r = 0; r < 4; r++) acc[i][j][r] = 0.f;

    const bool aK = (p.sAk == 1);     // A contiguous along k
    const bool bN = (p.sBn == 1);     // B contiguous along n

    // All M/N/K dims used are divisible by 4, so a 16B cp covers in-bounds data
    // whenever its first element is in bounds.
    auto issueA = [&](int k0, int stg) {
        float* dst = sA + stg * STGF;
#pragma unroll
        for (int i = 0; i < 2; i++) {
            int lin = tid + i * 256;
            if (aK) {                           // row layout [128][20]
                int row = lin >> 2, kv = (lin & 3) * 4;
                int gm = m0 + row, gk = k0 + kv;
                bool ok = (gm < p.M) && (gk < Keff);
                const float* src = ok ? (Ap + (long long)gm * p.sAm + gk) : Ap;
                cp16(&dst[row * 20 + kv], src, ok);
            } else {                            // col layout [16][132]
                int kr = lin >> 5, mv = (lin & 31) * 4;
                int gk = k0 + kr, gm = m0 + mv;
                bool ok = (gk < Keff) && (gm < p.M);
                const float* src = ok ? (Ap + (long long)gm + (long long)gk * p.sAk) : Ap;
                cp16(&dst[kr * 132 + mv], src, ok);
            }
        }
    };
    auto issueB = [&](int k0, int stg) {
        float* dst = sB + stg * STGF;
#pragma unroll
        for (int i = 0; i < 2; i++) {
            int lin = tid + i * 256;
            if (bN) {                           // col layout [16][132]
                int kr = lin >> 5, nv = (lin & 31) * 4;
                int gk = k0 + kr, gn = n0 + nv;
                bool ok = (gk < Keff) && (gn < p.N);
                const float* src = ok ? (Bp + (long long)gk * p.sBk + gn) : Bp;
                cp16(&dst[kr * 132 + nv], src, ok);
            } else {                            // row layout [128][20]
                int row = lin >> 2, kv = (lin & 3) * 4;
                int gn = n0 + row, gk = k0 + kv;
                bool ok = (gn < p.N) && (gk < Keff);
                const float* src = ok ? (Bp + (long long)gk * p.sBk + (long long)gn * p.sBn) : Bp;
                cp16(&dst[row * 20 + kv], src, ok);
            }
        }
    };

    int nk = (Keff + 15) >> 4;
#pragma unroll
    for (int s = 0; s < NSTG - 1; s++) {
        if (s < nk) { issueA(s << 4, s); issueB(s << 4, s); }
        CP_COMMIT();
    }

    for (int kt = 0; kt < nk; kt++) {
        int buf = kt % NSTG;
        asm volatile("cp.async.wait_group %0;\n" :: "n"(NSTG - 2));
        __syncthreads();
        // stage (kt+2)%NSTG was last read in iteration kt-1; all warps are past it.
        int nxt = kt + NSTG - 1;
        if (nxt < nk) { issueA(nxt << 4, nxt % NSTG); issueB(nxt << 4, nxt % NSTG); }
        CP_COMMIT();

        const float* Ab = sA + buf * STGF;
        const float* Bb = sB + buf * STGF;
#pragma unroll
        for (int s = 0; s < 2; s++) {
            int k8 = s * 8;
            unsigned af[4][4], bf[4][2];
            if (aK) {
#pragma unroll
                for (int mf = 0; mf < 4; mf++) {
                    int cm = wm * 64 + mf * 16 + lq;
                    af[mf][0] = f2tf(Ab[cm * 20 + k8 + lr]);
                    af[mf][1] = f2tf(Ab[(cm + 8) * 20 + k8 + lr]);
                    af[mf][2] = f2tf(Ab[cm * 20 + k8 + lr + 4]);
                    af[mf][3] = f2tf(Ab[(cm + 8) * 20 + k8 + lr + 4]);
                }
            } else {
#pragma unroll
                for (int mf = 0; mf < 4; mf++) {
                    int cm = wm * 64 + mf * 16 + lq;
                    af[mf][0] = f2tf(Ab[(k8 + lr) * 132 + cm]);
                    af[mf][1] = f2tf(Ab[(k8 + lr) * 132 + cm + 8]);
                    af[mf][2] = f2tf(Ab[(k8 + lr + 4) * 132 + cm]);
                    af[mf][3] = f2tf(Ab[(k8 + lr + 4) * 132 + cm + 8]);
                }
            }
            if (bN) {
#pragma unroll
                for (int nf = 0; nf < 4; nf++) {
                    int cn = wn * 32 + nf * 8 + lq;
                    bf[nf][0] = f2tf(Bb[(k8 + lr) * 132 + cn]);
                    bf[nf][1] = f2tf(Bb[(k8 + lr + 4) * 132 + cn]);
                }
            } else {
#pragma unroll
                for (int nf = 0; nf < 4; nf++) {
                    int cn = wn * 32 + nf * 8 + lq;
                    bf[nf][0] = f2tf(Bb[cn * 20 + k8 + lr]);
                    bf[nf][1] = f2tf(Bb[cn * 20 + k8 + lr + 4]);
                }
            }
#pragma unroll
            for (int mf = 0; mf < 4; mf++)
#pragma unroll
                for (int nf = 0; nf < 4; nf++)
                    mma_tf32(acc[mf][nf], af[mf], bf[nf]);
        }
    }

    long long offO = (long long)bo * p.bO + (long long)bi * p.bO2;
    long long offBias = p.bBias * bz;
#pragma unroll
    for (int mf = 0; mf < 4; mf++) {
        int row = m0 + wm * 64 + mf * 16 + lq;
#pragma unroll
        for (int nf = 0; nf < 4; nf++) {
            int col = n0 + wn * 32 + nf * 8 + lr * 2;
            epi_write(p, row,     col,     acc[mf][nf][0], offO, offBias);
            epi_write(p, row,     col + 1, acc[mf][nf][1], offO, offBias);
            epi_write(p, row + 8, col,     acc[mf][nf][2], offO, offBias);
            epi_write(p, row + 8, col + 1, acc[mf][nf][3], offO, offBias);
        }
    }
}

// ---------------- elementwise / reduction kernels ----------------
__global__ void pool_k(const float* mem, float* pool) {
    int i = blockIdx.x * 256 + threadIdx.x;
    if (i >= Bn * Mn * Cn) return;
    int c = i % Cn;
    int r = i / Cn;
    int m = r % Mn;
    int b = r / Mn;
    const float* pp = mem + ((long long)b * Tn + m * (Tn / Mn)) * Cn + c;
    float s = 0.f;
#pragma unroll 8
    for (int j = 0; j < Tn / Mn; j++) s += pp[(long long)j * Cn];
    pool[i] = s * (1.f / (Tn / Mn));
}

__global__ void build_xa_k(const float* retr, const float* persist, const float* x, float* xa) {
    long long i = (long long)blockIdx.x * 256 + threadIdx.x;
    if (i >= (long long)Bn * TAn * Cn) return;
    int c = (int)(i % Cn);
    long long r = i / Cn;
    int t = (int)(r % TAn);
    int b = (int)(r / TAn);
    float v;
    if (t < Mn)        v = retr[((long long)b * Mn + t) * Cn + c];
    else if (t < PREn) v = persist[(long long)(t - Mn) * Cn + c];
    else               v = x[((long long)b * Tn + (t - PREn)) * Cn + c];
    xa[i] = v;
}

__global__ void ln_k(const float* x, float* o, const float* w, const float* bb) {
    long long row = blockIdx.x;
    const float* xr = x + row * Cn;
    float* orow = o + row * Cn;
    int t = threadIdx.x;
    __shared__ float s1[256], s2[256];
    float v0 = xr[t], v1 = xr[t + 256], v2 = xr[t + 512];
    s1[t] = v0 + v1 + v2;
    s2[t] = v0 * v0 + v1 * v1 + v2 * v2;
    __syncthreads();
    for (int st = 128; st > 0; st >>= 1) {
        if (t < st) { s1[t] += s1[t + st]; s2[t] += s2[t + st]; }
        __syncthreads();
    }
    float mean = s1[0] * (1.f / Cn);
    float var  = s2[0] * (1.f / Cn) - mean * mean;
    float rs = rsqrtf(var + 1e-5f);
    orow[t]       = (v0 - mean) * rs * w[t]       + bb[t];
    orow[t + 256] = (v1 - mean) * rs * w[t + 256] + bb[t + 256];
    orow[t + 512] = (v2 - mean) * rs * w[t + 512] + bb[t + 512];
}

// softmax over the causally-valid prefix of each row; zero-fill to the
// y-GEMM k-cap boundary so capped k-loops read exact zeros.
__global__ void softmax_k(float* a) {
    long long row = blockIdx.x;
    int m = (int)(row % TAn);
    float* r = a + row * TAn;
    int lim = (m < PREn) ? TAn : (m + 1);
    int end = (m < 128) ? TAn : (((m >> 7) + 1) << 7);
    if (end > TAn) end = TAn;
    int t = threadIdx.x;
    __shared__ float red[256];
    float mx = -1e30f;
    for (int c = t; c < lim; c += 256) mx = fmaxf(mx, r[c]);
    red[t] = mx; __syncthreads();
    for (int st = 128; st > 0; st >>= 1) { if (t < st) red[t] = fmaxf(red[t], red[t + st]); __syncthreads(); }
    mx = red[0]; __syncthreads();
    float s = 0.f;
    for (int c = t; c < lim; c += 256) { float e = __expf(r[c] - mx); r[c] = e; s += e; }
    red[t] = s; __syncthreads();
    for (int st = 128; st > 0; st >>= 1) { if (t < st) red[t] += red[t + st]; __syncthreads(); }
    float inv = 1.f / red[0];
    for (int c = t; c < lim; c += 256) r[c] *= inv;
    for (int c = lim + t; c < end; c += 256) r[c] = 0.f;
}

__global__ void copyout_k(const float* xa, float* go, float* dout) {
    long long i = (long long)blockIdx.x * 256 + threadIdx.x;
    if (i >= (long long)Bn * Tn * Cn) return;
    int c = (int)(i % Cn);
    long long r = i / Cn;
    int t = (int)(r % Tn);
    int b = (int)(r / Tn);
    float v = xa[((long long)b * TAn + PREn + t) * Cn + c];
    go[i] = v;
    dout[i] = v;
}

__global__ void colsum_part_k(const float* src, float* part, int cols) {
    int i = blockIdx.x * 256 + threadIdx.x;
    int total = SLICES * Bn * cols;
    if (i >= total) return;
    int s = i / (Bn * cols);
    int rem = i % (Bn * cols);
    int b = rem / cols, c = rem % cols;
    const float* p = src + ((long long)b * Tn + s * (Tn / SLICES)) * cols + c;
    float g = 0.f;
    for (int r = 0; r < Tn / SLICES; r++) g += p[(long long)r * cols];
    part[i] = g;
}

__global__ void colsum_fin_k(const float* part, const float* memb, const float* mom,
                             float* nb, float* nm, int n) {
    int i = blockIdx.x * 256 + threadIdx.x;
    if (i >= n) return;
    float g = 0.f;
    for (int s = 0; s < SLICES; s++) g += part[(long long)s * n + i];
    float m2 = 0.9f * mom[i] + g;
    nm[i] = m2;
    nb[i] = 0.999f * memb[i] - 0.01f * m2;
}

// ---------------- host ----------------
static void run_gemm(const float* A, long long sAm, long long sAk, long long bA, long long bA2,
                     const float* Bm, long long sBk, long long sBn, long long bB, long long bB2,
                     float* O, long long sOm, long long sOn, long long bO, long long bO2,
                     int M, int N, int K, int batch, int binner,
                     const float* bias, long long bBias, int mode,
                     float* O2, const float* aux, const float* aux2, float scale, int tri = 0)
{
    GP p;
    p.A = A; p.Bm = Bm; p.O = O; p.O2 = O2; p.bias = bias; p.aux = aux; p.aux2 = aux2;
    p.M = M; p.N = N; p.K = K; p.binner = binner;
    p.sAm = sAm; p.sAk = sAk; p.bA = bA; p.bA2 = bA2;
    p.sBk = sBk; p.sBn = sBn; p.bB = bB; p.bB2 = bB2;
    p.sOm = sOm; p.sOn = sOn; p.bO = bO; p.bO2 = bO2;
    p.bBias = bBias; p.mode = mode; p.prefix = PREn; p.tri = tri; p.scale = scale;
    cudaFuncSetAttribute(gemm_tc, cudaFuncAttributeMaxDynamicSharedMemorySize, SMEM_BYTES);
    dim3 g((N + 127) / 128, (M + 127) / 128, batch);
    gemm_tc<<<g, 256, SMEM_BYTES>>>(p);
}

extern "C" void kernel_launch(void* const* d_in, const int* in_sizes, int n_in,
                              void* d_out, int out_size) {
    const float* x           = (const float*)d_in[0];
    const float* persist     = (const float*)d_in[1];
    const float* ln1_w       = (const float*)d_in[2];
    const float* ln1_b       = (const float*)d_in[3];
    const float* ln2_w       = (const float*)d_in[4];
    const float* ln2_b       = (const float*)d_in[5];
    const float* attn_w      = (const float*)d_in[6];
    const float* attn_b      = (const float*)d_in[7];
    const float* attn_proj_w = (const float*)d_in[8];
    const float* attn_proj_b = (const float*)d_in[9];
    const float* fc_w        = (const float*)d_in[10];
    const float* fc_b        = (const float*)d_in[11];
    const float* mlp_proj_w  = (const float*)d_in[12];
    const float* mlp_proj_b  = (const float*)d_in[13];
    const float* q_w         = (const float*)d_in[14];
    const float* q_b         = (const float*)d_in[15];
    const float* k_w         = (const float*)d_in[16];
    const float* k_b         = (const float*)d_in[17];
    const float* v_w         = (const float*)d_in[18];
    const float* v_b         = (const float*)d_in[19];
    const float* o_w         = (const float*)d_in[20];
    const float* o_b         = (const float*)d_in[21];
    const float* mem_w0      = (const float*)d_in[22];
    const float* mem_b0      = (const float*)d_in[23];
    const float* mem_w1      = (const float*)d_in[24];
    const float* mem_b1      = (const float*)d_in[25];
    const float* mom_w0      = (const float*)d_in[26];
    const float* mom_b0      = (const float*)d_in[27];
    const float* mom_w1      = (const float*)d_in[28];
    const float* mom_b1      = (const float*)d_in[29];
    float* out = (float*)d_out;

    float *Q, *HB, *MEM, *POOL, *RETR, *XA, *HLN, *QKV, *ATT, *Y, *FC, *OUT, *KEY, *VAL,
          *PRE, *HH, *DPR, *DHH, *P0, *P1;
    cudaGetSymbolAddress((void**)&Q, g_q);
    cudaGetSymbolAddress((void**)&HB, g_hbuf);
    cudaGetSymbolAddress((void**)&MEM, g_mem);
    cudaGetSymbolAddress((void**)&POOL, g_pool);
    cudaGetSymbolAddress((void**)&RETR, g_retr);
    cudaGetSymbolAddress((void**)&XA, g_xa);
    cudaGetSymbolAddress((void**)&HLN, g_hln);
    cudaGetSymbolAddress((void**)&QKV, g_qkv);
    cudaGetSymbolAddress((void**)&ATT, g_att);
    cudaGetSymbolAddress((void**)&Y, g_y);
    cudaGetSymbolAddress((void**)&FC, g_fc);
    cudaGetSymbolAddress((void**)&OUT, g_o);
    cudaGetSymbolAddress((void**)&KEY, g_key);
    cudaGetSymbolAddress((void**)&VAL, g_val);
    cudaGetSymbolAddress((void**)&PRE, g_pre);
    cudaGetSymbolAddress((void**)&HH, g_hh);
    cudaGetSymbolAddress((void**)&DPR, g_dpr);
    cudaGetSymbolAddress((void**)&DHH, g_dhh);
    cudaGetSymbolAddress((void**)&P0, g_p0);
    cudaGetSymbolAddress((void**)&P1, g_p1);

    const long long TC   = (long long)Tn * Cn;
    const long long TH   = (long long)Tn * HIDn;
    const long long CH   = (long long)Cn * HIDn;
    const long long HC   = (long long)HIDn * Cn;
    const long long TAC  = (long long)TAn * Cn;
    const long long TA3C = (long long)TAn * 3 * Cn;
    const long long TATA = (long long)TAn * TAn;

    const long long o_nw0  = 6291456LL;
    const long long o_nb0  = 15728640LL;
    const long long o_nw1  = 15740928LL;
    const long long o_nb1  = 25178112LL;
    const long long o_nmw0 = 25184256LL;
    const long long o_nmb0 = 34621440LL;
    const long long o_nmw1 = 34633728LL;
    const long long o_nmb1 = 44070912LL;

    run_gemm(x, Cn, 1, 0, 0,  q_w, 1, Cn, 0, 0,  Q, Cn, 1, 0, 0,
             Bn * Tn, Cn, Cn, 1, 1, q_b, 0, 0, nullptr, nullptr, nullptr, 0.f);
    run_gemm(Q, Cn, 1, TC, 0,  mem_w0, 1, Cn, HC, 0,  HB, HIDn, 1, TH, 0,
             Tn, HIDn, Cn, Bn, 1, mem_b0, HIDn, 1, nullptr, nullptr, nullptr, 0.f);
    run_gemm(HB, HIDn, 1, TH, 0,  mem_w1, 1, HIDn, CH, 0,  MEM, Cn, 1, TC, 0,
             Tn, Cn, HIDn, Bn, 1, mem_b1, Cn, 0, nullptr, nullptr, nullptr, 0.f);
    pool_k<<<(Bn * Mn * Cn + 255) / 256, 256>>>(MEM, POOL);
    run_gemm(POOL, Cn, 1, 0, 0,  o_w, 1, Cn, 0, 0,  RETR, Cn, 1, 0, 0,
             Bn * Mn, Cn, Cn, 1, 1, o_b, 0, 0, nullptr, nullptr, nullptr, 0.f);
    build_xa_k<<<(int)(((long long)Bn * TAn * Cn + 255) / 256), 256>>>(RETR, persist, x, XA);
    ln_k<<<Bn * TAn, 256>>>(XA, HLN, ln1_w, ln1_b);
    run_gemm(HLN, Cn, 1, 0, 0,  attn_w, 1, Cn, 0, 0,  QKV, 3 * Cn, 1, 0, 0,
             Bn * TAn, 3 * Cn, Cn, 1, 1, attn_b, 0, 0, nullptr, nullptr, nullptr, 0.f);
    // scores = scale * Q K^T with prefix-causal mask; skip fully-masked blocks
    run_gemm(QKV, 3 * Cn, 1, TA3C, 64,  QKV + Cn, 1, 3 * Cn, TA3C, 64,
             ATT, TAn, 1, (long long)Hn * TATA, TATA,
             TAn, TAn, 64, Bn * Hn, Hn, nullptr, 0, 3, nullptr, nullptr, nullptr, 0.125f, 1);
    softmax_k<<<Bn * Hn * TAn, 256>>>(ATT);
    // y = att @ V with per-block K cap
    run_gemm(ATT, TAn, 1, (long long)Hn * TATA, TATA,  QKV + 2 * Cn, 3 * Cn, 1, TA3C, 64,
             Y, Cn, 1, TAC, 64,
             TAn, 64, TAn, Bn * Hn, Hn, nullptr, 0, 0, nullptr, nullptr, nullptr, 0.f, 2);
    run_gemm(Y, Cn, 1, 0, 0,  attn_proj_w, 1, Cn, 0, 0,  XA, Cn, 1, 0, 0,
             Bn * TAn, Cn, Cn, 1, 1, attn_proj_b, 0, 4, nullptr, XA, nullptr, 0.f);
    ln_k<<<Bn * TAn, 256>>>(XA, HLN, ln2_w, ln2_b);
    run_gemm(HLN, Cn, 1, 0, 0,  fc_w, 1, Cn, 0, 0,  FC, 4 * Cn, 1, 0, 0,
             Bn * TAn, 4 * Cn, Cn, 1, 1, fc_b, 0, 2, nullptr, nullptr, nullptr, 0.f);
    run_gemm(FC, 4 * Cn, 1, 0, 0,  mlp_proj_w, 1, 4 * Cn, 0, 0,  XA, Cn, 1, 0, 0,
             Bn * TAn, Cn, 4 * Cn, 1, 1, mlp_proj_b, 0, 4, nullptr, XA, nullptr, 0.f);
    copyout_k<<<(int)(((long long)Bn * Tn * Cn + 255) / 256), 256>>>(XA, OUT, out);
    run_gemm(OUT, Cn, 1, 0, 0,  k_w, 1, Cn, 0, 0,  KEY, Cn, 1, 0, 0,
             Bn * Tn, Cn, Cn, 1, 1, k_b, 0, 0, nullptr, nullptr, nullptr, 0.f);
    run_gemm(OUT, Cn, 1, 0, 0,  v_w, 1, Cn, 0, 0,  VAL, Cn, 1, 0, 0,
             Bn * Tn, Cn, Cn, 1, 1, v_b, 0, 0, nullptr, nullptr, nullptr, 0.f);
    run_gemm(KEY, Cn, 1, TC, 0,  mem_w0, 1, Cn, HC, 0,  HH, HIDn, 1, TH, 0,
             Tn, HIDn, Cn, Bn, 1, mem_b0, HIDn, 1, PRE, nullptr, nullptr, 0.f);
    run_gemm(HH, HIDn, 1, TH, 0,  mem_w1, 1, HIDn, CH, 0,  DPR, Cn, 1, TC, 0,
             Tn, Cn, HIDn, Bn, 1, mem_b1, Cn, 5, nullptr, VAL, nullptr,
             2.f / (float)(Tn * Cn));
    run_gemm(DPR, 1, Cn, TC, 0,  HH, HIDn, 1, TH, 0,  out + o_nw1, HIDn, 1, CH, 0,
             Cn, HIDn, Tn, Bn, 1, nullptr, 0, 7, out + o_nmw1, mem_w1, mom_w1, 0.f);
    run_gemm(DPR, Cn, 1, TC, 0,  mem_w1, HIDn, 1, CH, 0,  DHH, HIDn, 1, TH, 0,
             Tn, HIDn, Cn, Bn, 1, nullptr, 0, 6, nullptr, PRE, nullptr, 0.f);
    run_gemm(DHH, 1, HIDn, TH, 0,  KEY, Cn, 1, TC, 0,  out + o_nw0, Cn, 1, HC, 0,
             HIDn, Cn, Tn, Bn, 1, nullptr, 0, 7, out + o_nmw0, mem_w0, mom_w0, 0.f);
    colsum_part_k<<<(SLICES * Bn * Cn + 255) / 256, 256>>>(DPR, P1, Cn);
    colsum_fin_k<<<(Bn * Cn + 255) / 256, 256>>>(P1, mem_b1, mom_b1,
                                                 out + o_nb1, out + o_nmb1, Bn * Cn);
    colsum_part_k<<<(SLICES * Bn * HIDn + 255) / 256, 256>>>(DHH, P0, HIDn);
    colsum_fin_k<<<(Bn * HIDn + 255) / 256, 256>>>(P0, mem_b0, mom_b0,
                                                   out + o_nb0, out + o_nmb0, Bn * HIDn);
    (void)in_sizes; (void)n_in; (void)out_size;
}

// round 13
// speedup vs baseline: 1.6099x; 1.6099x over previous
#include <cuda_runtime.h>
#include <cuda_fp16.h>

#define Bn   8
#define Tn   1024
#define Cn   768
#define Hn   12
#define HIDn 1536
#define Mn   16
#define Pn   4
#define PREn 20
#define TAn  1044
#define KPAD 1056          // TAn padded to mult of 32 for y-GEMM K
#define SLICES 16

// ---------------- fp32 scratch ----------------
__device__ float g_q   [Bn*Tn*Cn];
__device__ float g_hbuf[Bn*Tn*HIDn];
__device__ float g_mem [Bn*Tn*Cn];
__device__ float g_pool[Bn*Mn*Cn];
__device__ float g_retr[Bn*Mn*Cn];
__device__ float g_xa  [Bn*TAn*Cn];
__device__ float g_qkv [Bn*TAn*3*Cn];
__device__ float g_att [Bn*Hn*TAn*TAn];
__device__ float g_y   [Bn*TAn*Cn];
__device__ float g_fc  [Bn*TAn*4*Cn];
__device__ float g_key [Bn*Tn*Cn];
__device__ float g_val [Bn*Tn*Cn];
__device__ float g_pre [Bn*Tn*HIDn];
__device__ float g_hh  [Bn*Tn*HIDn];
__device__ float g_dpr [Bn*Tn*Cn];
__device__ float g_dhh [Bn*Tn*HIDn];
__device__ float g_p0  [SLICES*Bn*HIDn];
__device__ float g_p1  [SLICES*Bn*Cn];

// ---------------- fp16 mirrors ----------------
__device__ __half h_x   [Bn*Tn*Cn];
__device__ __half h_q   [Bn*Tn*Cn];
__device__ __half h_hb  [Bn*Tn*HIDn];
__device__ __half h_pool[Bn*Mn*Cn];
__device__ __half h_hln [Bn*TAn*Cn];
__device__ __half h_qkv [Bn*TAn*3*Cn];
__device__ __half h_att [(long long)Bn*Hn*TAn*KPAD];
__device__ __half h_vt  [Bn*Hn*64*KPAD];
__device__ __half h_y   [Bn*TAn*Cn];
__device__ __half h_fc  [Bn*TAn*4*Cn];
__device__ __half h_out [Bn*Tn*Cn];
__device__ __half h_keyf[Bn*Tn*Cn];
__device__ __half h_keyt[Bn*Cn*Tn];
__device__ __half h_hh  [Bn*Tn*HIDn];
__device__ __half h_hht [Bn*HIDn*Tn];
__device__ __half h_dpr [Bn*Tn*Cn];
__device__ __half h_dprt[Bn*Cn*Tn];
__device__ __half h_dhht[Bn*HIDn*Tn];
// weight mirrors
__device__ __half h_wq  [Cn*Cn];
__device__ __half h_wk  [Cn*Cn];
__device__ __half h_wv  [Cn*Cn];
__device__ __half h_wo  [Cn*Cn];
__device__ __half h_wat [3*Cn*Cn];
__device__ __half h_wpr [Cn*Cn];
__device__ __half h_wfc [4*Cn*Cn];
__device__ __half h_wml [Cn*4*Cn];
__device__ __half h_wm0 [Bn*HIDn*Cn];
__device__ __half h_wm1 [Bn*Cn*HIDn];
__device__ __half h_wm1t[Bn*HIDn*Cn];

// ---------------- GEMM params ----------------
// A: half [M][lda] k-contig. B: half [N][ldb] k-contig. K multiple of 32.
struct GP {
    const __half* A; const __half* Bm; float* O; float* O2; __half* Oh;
    const float* bias; const float* aux; const float* aux2;
    int M, N, K, binner;
    long long lda, ldb, bA, bA2, bB, bB2;
    long long sOm, bO, bO2, bBias;
    int mode, prefix, tri;
    float scale, gscale;
};
// modes: 0 bias | 1 silu(+pre->O2) | 2 gelu | 3 attn scale+mask | 4 residual
//        5 dpred-unscaled | 6 silu-bwd(aux=pre) | 7 momentum (v*gscale)
// tri: 1 skip masked blocks, 2 cap K at m0+128

__device__ __forceinline__ void mma_f16(float* c, const unsigned* a, const unsigned* b) {
    asm volatile(
        "mma.sync.aligned.m16n8k16.row.col.f32.f16.f16.f32 "
        "{%0,%1,%2,%3}, {%4,%5,%6,%7}, {%8,%9}, {%0,%1,%2,%3};\n"
        : "+f"(c[0]), "+f"(c[1]), "+f"(c[2]), "+f"(c[3])
        : "r"(a[0]), "r"(a[1]), "r"(a[2]), "r"(a[3]), "r"(b[0]), "r"(b[1]));
}

__device__ __forceinline__ void cp16h(__half* dst, const __half* src, bool pred) {
    unsigned d = (unsigned)__cvta_generic_to_shared(dst);
    int sz = pred ? 16 : 0;
    asm volatile("cp.async.cg.shared.global [%0], [%1], 16, %2;\n"
                 :: "r"(d), "l"(src), "r"(sz));
}
#define CP_COMMIT() asm volatile("cp.async.commit_group;\n" ::)

__device__ __forceinline__ void epi_write(const GP& p, int m, int n, float v,
                                          long long offO, long long offBias) {
    if (m >= p.M || n >= p.N) return;
    long long o = offO + (long long)m * p.sOm + n;
    float bsv = p.bias ? p.bias[offBias + n] : 0.f;
    float outv = 0.f;
    switch (p.mode) {
        case 0: outv = v + bsv; p.O[o] = outv; break;
        case 1: { float z = v + bsv; if (p.O2) p.O2[o] = z;
                  float sg = 1.f / (1.f + __expf(-z)); outv = z * sg; p.O[o] = outv; } break;
        case 2: { float z = v + bsv; outv = 0.5f * z * (1.f + erff(z * 0.70710678118f));
                  p.O[o] = outv; } break;
        case 3: { float z = v * p.scale; if (m >= p.prefix && n > m) z = -1e30f;
                  outv = z; p.O[o] = z; } break;
        case 4: outv = p.aux[o] + v + bsv; p.O[o] = outv; break;
        case 5: outv = v + bsv - p.aux[o]; p.O[o] = outv; break;
        case 6: { float z = p.aux[o]; float sg = 1.f / (1.f + __expf(-z));
                  outv = v * sg * (1.f + z * (1.f - sg)); p.O[o] = outv; } break;
        case 7: { float g = v * p.gscale; float nm = 0.9f * p.aux2[o] + g;
                  p.O2[o] = nm; p.O[o] = 0.999f * p.aux[o] - 0.01f * nm; } break;
    }
    if (p.Oh) p.Oh[o] = __float2half(outv);
}

// ---- fp16 tensor-core GEMM: 128x128 block, k-tile 32, 8 warps, 2-stage cp.async ----
// smem row layout [128][40] halves (stride 40 -> conflict-free b32 fragment LDS)
__global__ void __launch_bounds__(256, 2) gemm_h(GP p) {
    __shared__ __half sA[2][128 * 40];
    __shared__ __half sB[2][128 * 40];
    int bz = blockIdx.z;
    int bo = bz / p.binner, bi = bz % p.binner;
    const __half* Ap = p.A  + (long long)bo * p.bA + (long long)bi * p.bA2;
    const __half* Bp = p.Bm + (long long)bo * p.bB + (long long)bi * p.bB2;
    int m0 = blockIdx.y * 128, n0 = blockIdx.x * 128;

    if (p.tri == 1 && m0 > 0 && n0 >= m0 + 128) return;
    int Keff = p.K;
    if (p.tri == 2 && m0 > 0 && m0 + 128 < Keff) Keff = m0 + 128;  // mult of 128

    int tid = threadIdx.x;
    int warp = tid >> 5, lane = tid & 31;
    int wm = warp & 1, wn = warp >> 1;      // warp tile 64(m) x 32(n)
    int lq = lane >> 2, lr = lane & 3;

    float acc[4][4][4];
#pragma unroll
    for (int i = 0; i < 4; i++)
#pragma unroll
        for (int j = 0; j < 4; j++)
#pragma unroll
            for (int r = 0; r < 4; r++) acc[i][j][r] = 0.f;

    auto issue = [&](int k0, int stg) {
#pragma unroll
        for (int i = 0; i < 2; i++) {
            int chunk = tid + i * 256;          // 512 chunks per operand
            int row = chunk >> 2, c4 = chunk & 3;
            int k = k0 + c4 * 8;
            int gm = m0 + row;
            bool okA = (gm < p.M);
            cp16h(&sA[stg][row * 40 + c4 * 8],
                  okA ? (Ap + (long long)gm * p.lda + k) : Ap, okA);
            int gn = n0 + row;
            bool okB = (gn < p.N);
            cp16h(&sB[stg][row * 40 + c4 * 8],
                  okB ? (Bp + (long long)gn * p.ldb + k) : Bp, okB);
        }
    };

    int nk = Keff >> 5;                      // K multiple of 32 (mirrors padded)
    issue(0, 0);
    CP_COMMIT();

    for (int kt = 0; kt < nk; kt++) {
        int buf = kt & 1;
        asm volatile("cp.async.wait_group 0;\n" ::);
        __syncthreads();
        if (kt + 1 < nk) { issue((kt + 1) << 5, buf ^ 1); CP_COMMIT(); }

        const __half* Ab = sA[buf];
        const __half* Bb = sB[buf];
#pragma unroll
        for (int s = 0; s < 2; s++) {
            int ks = s * 16;
            unsigned af[4][4], bf[4][2];
#pragma unroll
            for (int mf = 0; mf < 4; mf++) {
                int cm = wm * 64 + mf * 16 + lq;
                af[mf][0] = *(const unsigned*)&Ab[cm * 40 + ks + 2 * lr];
                af[mf][1] = *(const unsigned*)&Ab[(cm + 8) * 40 + ks + 2 * lr];
                af[mf][2] = *(const unsigned*)&Ab[cm * 40 + ks + 8 + 2 * lr];
                af[mf][3] = *(const unsigned*)&Ab[(cm + 8) * 40 + ks + 8 + 2 * lr];
            }
#pragma unroll
            for (int nf = 0; nf < 4; nf++) {
                int cn = wn * 32 + nf * 8 + lq;
                bf[nf][0] = *(const unsigned*)&Bb[cn * 40 + ks + 2 * lr];
                bf[nf][1] = *(const unsigned*)&Bb[cn * 40 + ks + 8 + 2 * lr];
            }
#pragma unroll
            for (int mf = 0; mf < 4; mf++)
#pragma unroll
                for (int nf = 0; nf < 4; nf++)
                    mma_f16(acc[mf][nf], af[mf], bf[nf]);
        }
    }

    long long offO = (long long)bo * p.bO + (long long)bi * p.bO2;
    long long offBias = p.bBias * bz;
#pragma unroll
    for (int mf = 0; mf < 4; mf++) {
        int row = m0 + wm * 64 + mf * 16 + lq;
#pragma unroll
        for (int nf = 0; nf < 4; nf++) {
            int col = n0 + wn * 32 + nf * 8 + lr * 2;
            epi_write(p, row,     col,     acc[mf][nf][0], offO, offBias);
            epi_write(p, row,     col + 1, acc[mf][nf][1], offO, offBias);
            epi_write(p, row + 8, col,     acc[mf][nf][2], offO, offBias);
            epi_write(p, row + 8, col + 1, acc[mf][nf][3], offO, offBias);
        }
    }
}

// ---------------- converts / transposes ----------------
__global__ void conv_k(const float* f, __half* h, long long n) {
    long long i = (long long)blockIdx.x * 256 + threadIdx.x;
    if (i < n) h[i] = __float2half(f[i]);
}

// batched tiled transpose+convert: in [z][R][Cc] fp32 -> out [z][Cc][R] fp16
__global__ void tconv_k(const float* in, __half* out, int R, int Cc) {
    __shared__ float tile[32][33];
    long long zo = (long long)blockIdx.z * R * Cc;
    int x = blockIdx.x * 32 + threadIdx.x;
#pragma unroll
    for (int j = threadIdx.y; j < 32; j += 8) {
        int y = blockIdx.y * 32 + j;
        if (x < Cc && y < R) tile[j][threadIdx.x] = in[zo + (long long)y * Cc + x];
    }
    __syncthreads();
    int ox = blockIdx.y * 32 + threadIdx.x;      // out col = in row
#pragma unroll
    for (int j = threadIdx.y; j < 32; j += 8) {
        int oy = blockIdx.x * 32 + j;            // out row = in col
        if (ox < R && oy < Cc) out[zo + (long long)oy * R + ox] = __float2half(tile[threadIdx.x][j]);
    }
}

// V gather-transpose: Vt[(b*H+h)*64+d][t<KPAD] from QKV fp32, zero-padded
__global__ void vt_k(const float* qkv, __half* vt) {
    long long i = (long long)blockIdx.x * 256 + threadIdx.x;
    long long total = (long long)Bn * Hn * 64 * KPAD;
    if (i >= total) return;
    int t = (int)(i % KPAD);
    long long r = i / KPAD;
    int d = (int)(r % 64);
    int h = (int)((r / 64) % Hn);
    int b = (int)(r / (64 * Hn));
    float v = (t < TAn)
        ? qkv[((long long)b * TAn + t) * (3 * Cn) + 2 * Cn + h * 64 + d] : 0.f;
    vt[i] = __float2half(v);
}

// ---------------- elementwise ----------------
__global__ void pool_k(const float* mem, float* pool, __half* poolh) {
    int i = blockIdx.x * 256 + threadIdx.x;
    if (i >= Bn * Mn * Cn) return;
    int c = i % Cn;
    int r = i / Cn;
    int m = r % Mn;
    int b = r / Mn;
    const float* pp = mem + ((long long)b * Tn + m * (Tn / Mn)) * Cn + c;
    float s = 0.f;
#pragma unroll 8
    for (int j = 0; j < Tn / Mn; j++) s += pp[(long long)j * Cn];
    float v = s * (1.f / (Tn / Mn));
    pool[i] = v;
    poolh[i] = __float2half(v);
}

__global__ void build_xa_k(const float* retr, const float* persist, const float* x, float* xa) {
    long long i = (long long)blockIdx.x * 256 + threadIdx.x;
    if (i >= (long long)Bn * TAn * Cn) return;
    int c = (int)(i % Cn);
    long long r = i / Cn;
    int t = (int)(r % TAn);
    int b = (int)(r / TAn);
    float v;
    if (t < Mn)        v = retr[((long long)b * Mn + t) * Cn + c];
    else if (t < PREn) v = persist[(long long)(t - Mn) * Cn + c];
    else               v = x[((long long)b * Tn + (t - PREn)) * Cn + c];
    xa[i] = v;
}

__global__ void ln_k(const float* x, __half* o, const float* w, const float* bb) {
    long long row = blockIdx.x;
    const float* xr = x + row * Cn;
    __half* orow = o + row * Cn;
    int t = threadIdx.x;
    __shared__ float s1[256], s2[256];
    float v0 = xr[t], v1 = xr[t + 256], v2 = xr[t + 512];
    s1[t] = v0 + v1 + v2;
    s2[t] = v0 * v0 + v1 * v1 + v2 * v2;
    __syncthreads();
    for (int st = 128; st > 0; st >>= 1) {
        if (t < st) { s1[t] += s1[t + st]; s2[t] += s2[t + st]; }
        __syncthreads();
    }
    float mean = s1[0] * (1.f / Cn);
    float var  = s2[0] * (1.f / Cn) - mean * mean;
    float rs = rsqrtf(var + 1e-5f);
    orow[t]       = __float2half((v0 - mean) * rs * w[t]       + bb[t]);
    orow[t + 256] = __float2half((v1 - mean) * rs * w[t + 256] + bb[t + 256]);
    orow[t + 512] = __float2half((v2 - mean) * rs * w[t + 512] + bb[t + 512]);
}

// softmax: read fp32 scores, write fp16 probs into KPAD-padded mirror (zero tail)
__global__ void softmax_k(float* a, __half* ah) {
    long long row = blockIdx.x;
    int m = (int)(row % TAn);
    float* r = a + row * TAn;
    __half* rh = ah + row * KPAD;
    int lim = (m < PREn) ? TAn : (m + 1);
    int t = threadIdx.x;
    __shared__ float red[256];
    float mx = -1e30f;
    for (int c = t; c < lim; c += 256) mx = fmaxf(mx, r[c]);
    red[t] = mx; __syncthreads();
    for (int st = 128; st > 0; st >>= 1) { if (t < st) red[t] = fmaxf(red[t], red[t + st]); __syncthreads(); }
    mx = red[0]; __syncthreads();
    float s = 0.f;
    for (int c = t; c < lim; c += 256) { float e = __expf(r[c] - mx); r[c] = e; s += e; }
    red[t] = s; __syncthreads();
    for (int st = 128; st > 0; st >>= 1) { if (t < st) red[t] += red[t + st]; __syncthreads(); }
    float inv = 1.f / red[0];
    for (int c = t; c < lim; c += 256) rh[c] = __float2half(r[c] * inv);
    for (int c = lim + t; c < KPAD; c += 256) rh[c] = __half(0.f);
}

__global__ void copyout_k(const float* xa, float* dout, __half* outh) {
    long long i = (long long)blockIdx.x * 256 + threadIdx.x;
    if (i >= (long long)Bn * Tn * Cn) return;
    int c = (int)(i % Cn);
    long long r = i / Cn;
    int t = (int)(r % Tn);
    int b = (int)(r / Tn);
    float v = xa[((long long)b * TAn + PREn + t) * Cn + c];
    dout[i] = v;
    outh[i] = __float2half(v);
}

__global__ void colsum_part_k(const float* src, float* part, int cols) {
    int i = blockIdx.x * 256 + threadIdx.x;
    int total = SLICES * Bn * cols;
    if (i >= total) return;
    int s = i / (Bn * cols);
    int rem = i % (Bn * cols);
    int b = rem / cols, c = rem % cols;
    const float* p = src + ((long long)b * Tn + s * (Tn / SLICES)) * cols + c;
    float g = 0.f;
    for (int r = 0; r < Tn / SLICES; r++) g += p[(long long)r * cols];
    part[i] = g;
}

__global__ void colsum_fin_k(const float* part, const float* memb, const float* mom,
                             float* nb, float* nm, int n, float gs) {
    int i = blockIdx.x * 256 + threadIdx.x;
    if (i >= n) return;
    float g = 0.f;
    for (int s = 0; s < SLICES; s++) g += part[(long long)s * n + i];
    float m2 = 0.9f * mom[i] + g * gs;
    nm[i] = m2;
    nb[i] = 0.999f * memb[i] - 0.01f * m2;
}

// ---------------- host ----------------
static void run_gemm(const __half* A, long long lda, long long bA, long long bA2,
                     const __half* Bm, long long ldb, long long bB, long long bB2,
                     float* O, long long sOm, long long bO, long long bO2,
                     int M, int N, int K, int batch, int binner,
                     const float* bias, long long bBias, int mode,
                     float* O2, __half* Oh, const float* aux, const float* aux2,
                     float scale, float gscale, int tri)
{
    GP p;
    p.A = A; p.Bm = Bm; p.O = O; p.O2 = O2; p.Oh = Oh;
    p.bias = bias; p.aux = aux; p.aux2 = aux2;
    p.M = M; p.N = N; p.K = K; p.binner = binner;
    p.lda = lda; p.ldb = ldb; p.bA = bA; p.bA2 = bA2; p.bB = bB; p.bB2 = bB2;
    p.sOm = sOm; p.bO = bO; p.bO2 = bO2; p.bBias = bBias;
    p.mode = mode; p.prefix = PREn; p.tri = tri; p.scale = scale; p.gscale = gscale;
    dim3 g((N + 127) / 128, (M + 127) / 128, batch);
    gemm_h<<<g, 256>>>(p);
}

static void conv(const float* f, __half* h, long long n) {
    conv_k<<<(int)((n + 255) / 256), 256>>>(f, h, n);
}
static void tconv(const float* in, __half* out, int R, int Cc, int batch) {
    dim3 g((Cc + 31) / 32, (R + 31) / 32, batch);
    tconv_k<<<g, dim3(32, 8)>>>(in, out, R, Cc);
}

extern "C" void kernel_launch(void* const* d_in, const int* in_sizes, int n_in,
                              void* d_out, int out_size) {
    const float* x           = (const float*)d_in[0];
    const float* persist     = (const float*)d_in[1];
    const float* ln1_w       = (const float*)d_in[2];
    const float* ln1_b       = (const float*)d_in[3];
    const float* ln2_w       = (const float*)d_in[4];
    const float* ln2_b       = (const float*)d_in[5];
    const float* attn_w      = (const float*)d_in[6];
    const float* attn_b      = (const float*)d_in[7];
    const float* attn_proj_w = (const float*)d_in[8];
    const float* attn_proj_b = (const float*)d_in[9];
    const float* fc_w        = (const float*)d_in[10];
    const float* fc_b        = (const float*)d_in[11];
    const float* mlp_proj_w  = (const float*)d_in[12];
    const float* mlp_proj_b  = (const float*)d_in[13];
    const float* q_w         = (const float*)d_in[14];
    const float* q_b         = (const float*)d_in[15];
    const float* k_w         = (const float*)d_in[16];
    const float* k_b         = (const float*)d_in[17];
    const float* v_w         = (const float*)d_in[18];
    const float* v_b         = (const float*)d_in[19];
    const float* o_w         = (const float*)d_in[20];
    const float* o_b         = (const float*)d_in[21];
    const float* mem_w0      = (const float*)d_in[22];
    const float* mem_b0      = (const float*)d_in[23];
    const float* mem_w1      = (const float*)d_in[24];
    const float* mem_b1      = (const float*)d_in[25];
    const float* mom_w0      = (const float*)d_in[26];
    const float* mom_b0      = (const float*)d_in[27];
    const float* mom_w1      = (const float*)d_in[28];
    const float* mom_b1      = (const float*)d_in[29];
    float* out = (float*)d_out;

    // fp32 scratch
    float *Q, *HB, *MEM, *POOL, *RETR, *XA, *QKV, *ATT, *Y, *FC, *KEY, *VAL,
          *PRE, *HH, *DPR, *DHH, *P0, *P1;
    cudaGetSymbolAddress((void**)&Q, g_q);
    cudaGetSymbolAddress((void**)&HB, g_hbuf);
    cudaGetSymbolAddress((void**)&MEM, g_mem);
    cudaGetSymbolAddress((void**)&POOL, g_pool);
    cudaGetSymbolAddress((void**)&RETR, g_retr);
    cudaGetSymbolAddress((void**)&XA, g_xa);
    cudaGetSymbolAddress((void**)&QKV, g_qkv);
    cudaGetSymbolAddress((void**)&ATT, g_att);
    cudaGetSymbolAddress((void**)&Y, g_y);
    cudaGetSymbolAddress((void**)&FC, g_fc);
    cudaGetSymbolAddress((void**)&KEY, g_key);
    cudaGetSymbolAddress((void**)&VAL, g_val);
    cudaGetSymbolAddress((void**)&PRE, g_pre);
    cudaGetSymbolAddress((void**)&HH, g_hh);
    cudaGetSymbolAddress((void**)&DPR, g_dpr);
    cudaGetSymbolAddress((void**)&DHH, g_dhh);
    cudaGetSymbolAddress((void**)&P0, g_p0);
    cudaGetSymbolAddress((void**)&P1, g_p1);
    // half mirrors
    __half *XH, *QH, *HBH, *POOLH, *HLNH, *QKVH, *ATTH, *VTH, *YH, *FCH, *OUTH,
           *KEYH, *KEYT, *HHH, *HHT, *DPRH, *DPRT, *DHHT,
           *WQ, *WK, *WV, *WO, *WAT, *WPR, *WFC, *WML, *WM0, *WM1, *WM1T;
    cudaGetSymbolAddress((void**)&XH, h_x);
    cudaGetSymbolAddress((void**)&QH, h_q);
    cudaGetSymbolAddress((void**)&HBH, h_hb);
    cudaGetSymbolAddress((void**)&POOLH, h_pool);
    cudaGetSymbolAddress((void**)&HLNH, h_hln);
    cudaGetSymbolAddress((void**)&QKVH, h_qkv);
    cudaGetSymbolAddress((void**)&ATTH, h_att);
    cudaGetSymbolAddress((void**)&VTH, h_vt);
    cudaGetSymbolAddress((void**)&YH, h_y);
    cudaGetSymbolAddress((void**)&FCH, h_fc);
    cudaGetSymbolAddress((void**)&OUTH, h_out);
    cudaGetSymbolAddress((void**)&KEYH, h_keyf);
    cudaGetSymbolAddress((void**)&KEYT, h_keyt);
    cudaGetSymbolAddress((void**)&HHH, h_hh);
    cudaGetSymbolAddress((void**)&HHT, h_hht);
    cudaGetSymbolAddress((void**)&DPRH, h_dpr);
    cudaGetSymbolAddress((void**)&DPRT, h_dprt);
    cudaGetSymbolAddress((void**)&DHHT, h_dhht);
    cudaGetSymbolAddress((void**)&WQ, h_wq);
    cudaGetSymbolAddress((void**)&WK, h_wk);
    cudaGetSymbolAddress((void**)&WV, h_wv);
    cudaGetSymbolAddress((void**)&WO, h_wo);
    cudaGetSymbolAddress((void**)&WAT, h_wat);
    cudaGetSymbolAddress((void**)&WPR, h_wpr);
    cudaGetSymbolAddress((void**)&WFC, h_wfc);
    cudaGetSymbolAddress((void**)&WML, h_wml);
    cudaGetSymbolAddress((void**)&WM0, h_wm0);
    cudaGetSymbolAddress((void**)&WM1, h_wm1);
    cudaGetSymbolAddress((void**)&WM1T, h_wm1t);

    const long long TC  = (long long)Tn * Cn;
    const long long TH  = (long long)Tn * HIDn;
    const long long CH  = (long long)Cn * HIDn;
    const long long HC  = (long long)HIDn * Cn;
    const long long TAC = (long long)TAn * Cn;
    const long long TATA = (long long)TAn * TAn;
    const float GS = 2.f / (float)(Tn * Cn);

    const long long o_nw0  = 6291456LL;
    const long long o_nb0  = 15728640LL;
    const long long o_nw1  = 15740928LL;
    const long long o_nb1  = 25178112LL;
    const long long o_nmw0 = 25184256LL;
    const long long o_nmb0 = 34621440LL;
    const long long o_nmw1 = 34633728LL;
    const long long o_nmb1 = 44070912LL;

    // ---- input converts ----
    conv(x, XH, (long long)Bn * TC);
    conv(q_w, WQ, (long long)Cn * Cn);
    conv(k_w, WK, (long long)Cn * Cn);
    conv(v_w, WV, (long long)Cn * Cn);
    conv(o_w, WO, (long long)Cn * Cn);
    conv(attn_w, WAT, (long long)3 * Cn * Cn);
    conv(attn_proj_w, WPR, (long long)Cn * Cn);
    conv(fc_w, WFC, (long long)4 * Cn * Cn);
    conv(mlp_proj_w, WML, (long long)Cn * 4 * Cn);
    conv(mem_w0, WM0, (long long)Bn * HC);
    conv(mem_w1, WM1, (long long)Bn * CH);
    tconv(mem_w1, WM1T, Cn, HIDn, Bn);   // [b][c][h] -> [b][h][c]

    // 1. q = x @ q_w^T + q_b
    run_gemm(XH, Cn, 0, 0,  WQ, Cn, 0, 0,  Q, Cn, 0, 0,
             Bn * Tn, Cn, Cn, 1, 1, q_b, 0, 0, nullptr, QH, nullptr, nullptr, 0.f, 0.f, 0);
    // 2. h = silu(q @ w0^T + b0)
    run_gemm(QH, Cn, TC, 0,  WM0, Cn, HC, 0,  HB, HIDn, TH, 0,
             Tn, HIDn, Cn, Bn, 1, mem_b0, HIDn, 1, nullptr, HBH, nullptr, nullptr, 0.f, 0.f, 0);
    // 3. mem = h @ w1^T + b1
    run_gemm(HBH, HIDn, TH, 0,  WM1, HIDn, CH, 0,  MEM, Cn, TC, 0,
             Tn, Cn, HIDn, Bn, 1, mem_b1, Cn, 0, nullptr, nullptr, nullptr, nullptr, 0.f, 0.f, 0);
    pool_k<<<(Bn * Mn * Cn + 255) / 256, 256>>>(MEM, POOL, POOLH);
    // 5. retrieved = pooled @ o_w^T + o_b
    run_gemm(POOLH, Cn, 0, 0,  WO, Cn, 0, 0,  RETR, Cn, 0, 0,
             Bn * Mn, Cn, Cn, 1, 1, o_b, 0, 0, nullptr, nullptr, nullptr, nullptr, 0.f, 0.f, 0);
    build_xa_k<<<(int)(((long long)Bn * TAn * Cn + 255) / 256), 256>>>(RETR, persist, x, XA);
    ln_k<<<Bn * TAn, 256>>>(XA, HLNH, ln1_w, ln1_b);
    // qkv
    run_gemm(HLNH, Cn, 0, 0,  WAT, Cn, 0, 0,  QKV, 3 * Cn, 0, 0,
             Bn * TAn, 3 * Cn, Cn, 1, 1, attn_b, 0, 0, nullptr, QKVH, nullptr, nullptr, 0.f, 0.f, 0);
    vt_k<<<(int)(((long long)Bn * Hn * 64 * KPAD + 255) / 256), 256>>>(QKV, VTH);
    // scores
    run_gemm(QKVH, 3 * Cn, (long long)TAn * 3 * Cn, 64,
             QKVH + Cn, 3 * Cn, (long long)TAn * 3 * Cn, 64,
             ATT, TAn, (long long)Hn * TATA, TATA,
             TAn, TAn, 64, Bn * Hn, Hn, nullptr, 0, 3,
             nullptr, nullptr, nullptr, nullptr, 0.125f, 0.f, 1);
    softmax_k<<<Bn * Hn * TAn, 256>>>(ATT, ATTH);
    // y = att @ V
    run_gemm(ATTH, KPAD, (long long)Hn * TAn * KPAD, (long long)TAn * KPAD,
             VTH, KPAD, (long long)Hn * 64 * KPAD, (long long)64 * KPAD,
             Y, Cn, TAC, 64,
             TAn, 64, KPAD, Bn * Hn, Hn, nullptr, 0, 0,
             nullptr, YH, nullptr, nullptr, 0.f, 0.f, 2);
    // attn proj + residual
    run_gemm(YH, Cn, 0, 0,  WPR, Cn, 0, 0,  XA, Cn, 0, 0,
             Bn * TAn, Cn, Cn, 1, 1, attn_proj_b, 0, 4, nullptr, nullptr, XA, nullptr, 0.f, 0.f, 0);
    ln_k<<<Bn * TAn, 256>>>(XA, HLNH, ln2_w, ln2_b);
    // fc gelu
    run_gemm(HLNH, Cn, 0, 0,  WFC, Cn, 0, 0,  FC, 4 * Cn, 0, 0,
             Bn * TAn, 4 * Cn, Cn, 1, 1, fc_b, 0, 2, nullptr, FCH, nullptr, nullptr, 0.f, 0.f, 0);
    // mlp proj + residual
    run_gemm(FCH, 4 * Cn, 0, 0,  WML, 4 * Cn, 0, 0,  XA, Cn, 0, 0,
             Bn * TAn, Cn, 4 * Cn, 1, 1, mlp_proj_b, 0, 4, nullptr, nullptr, XA, nullptr, 0.f, 0.f, 0);
    copyout_k<<<(int)(((long long)Bn * TC + 255) / 256), 256>>>(XA, out, OUTH);
    // keys / vals
    run_gemm(OUTH, Cn, 0, 0,  WK, Cn, 0, 0,  KEY, Cn, 0, 0,
             Bn * Tn, Cn, Cn, 1, 1, k_b, 0, 0, nullptr, KEYH, nullptr, nullptr, 0.f, 0.f, 0);
    run_gemm(OUTH, Cn, 0, 0,  WV, Cn, 0, 0,  VAL, Cn, 0, 0,
             Bn * Tn, Cn, Cn, 1, 1, v_b, 0, 0, nullptr, nullptr, nullptr, nullptr, 0.f, 0.f, 0);
    tconv(KEY, KEYT, Tn, Cn, Bn);
    // pre/hh
    run_gemm(KEYH, Cn, TC, 0,  WM0, Cn, HC, 0,  HH, HIDn, TH, 0,
             Tn, HIDn, Cn, Bn, 1, mem_b0, HIDn, 1, PRE, HHH, nullptr, nullptr, 0.f, 0.f, 0);
    tconv(HH, HHT, Tn, HIDn, Bn);
    // dpred (UNSCALED; scale applied via gscale downstream)
    run_gemm(HHH, HIDn, TH, 0,  WM1, HIDn, CH, 0,  DPR, Cn, TC, 0,
             Tn, Cn, HIDn, Bn, 1, mem_b1, Cn, 5, nullptr, DPRH, VAL, nullptr, 0.f, 0.f, 0);
    tconv(DPR, DPRT, Tn, Cn, Bn);
    // g_w1 + update
    run_gemm(DPRT, Tn, (long long)Cn * Tn, 0,  HHT, Tn, (long long)HIDn * Tn, 0,
             out + o_nw1, HIDn, CH, 0,
             Cn, HIDn, Tn, Bn, 1, nullptr, 0, 7,
             out + o_nmw1, nullptr, mem_w1, mom_w1, 0.f, GS, 0);
    // dh (unscaled)
    run_gemm(DPRH, Cn, TC, 0,  WM1T, Cn, HC, 0,  DHH, HIDn, TH, 0,
             Tn, HIDn, Cn, Bn, 1, nullptr, 0, 6, nullptr, nullptr, PRE, nullptr, 0.f, 0.f, 0);
    tconv(DHH, DHHT, Tn, HIDn, Bn);
    // g_w0 + update
    run_gemm(DHHT, Tn, (long long)HIDn * Tn, 0,  KEYT, Tn, (long long)Cn * Tn, 0,
             out + o_nw0, Cn, HC, 0,
             HIDn, Cn, Tn, Bn, 1, nullptr, 0, 7,
             out + o_nmw0, nullptr, mem_w0, mom_w0, 0.f, GS, 0);
    // bias grads
    colsum_part_k<<<(SLICES * Bn * Cn + 255) / 256, 256>>>(DPR, P1, Cn);
    colsum_fin_k<<<(Bn * Cn + 255) / 256, 256>>>(P1, mem_b1, mom_b1,
                                                 out + o_nb1, out + o_nmb1, Bn * Cn, GS);
    colsum_part_k<<<(SLICES * Bn * HIDn + 255) / 256, 256>>>(DHH, P0, HIDn);
    colsum_fin_k<<<(Bn * HIDn + 255) / 256, 256>>>(P0, mem_b0, mom_b0,
                                                   out + o_nb0, out + o_nmb0, Bn * HIDn, GS);
    (void)in_sizes; (void)n_in; (void)out_size;
}

// round 14
// speedup vs baseline: 1.6805x; 1.0439x over previous
#include <cuda_runtime.h>
#include <cuda_fp16.h>

#define Bn   8
#define Tn   1024
#define Cn   768
#define Hn   12
#define HIDn 1536
#define Mn   16
#define Pn   4
#define PREn 20
#define TAn  1044
#define KPAD 1056          // TAn padded to mult of 32 for y-GEMM K / ATTH row stride
#define SLICES 16

// ---------------- fp32 scratch (only what still has fp32 consumers) ----------------
__device__ float g_mem [Bn*Tn*Cn];
__device__ float g_pool[Bn*Mn*Cn];
__device__ float g_retr[Bn*Mn*Cn];
__device__ float g_xa  [Bn*TAn*Cn];
__device__ float g_val [Bn*Tn*Cn];
__device__ float g_pre [Bn*Tn*HIDn];
__device__ float g_dpr [Bn*Tn*Cn];
__device__ float g_dhh [Bn*Tn*HIDn];
__device__ float g_p0  [SLICES*Bn*HIDn];
__device__ float g_p1  [SLICES*Bn*Cn];

// ---------------- fp16 mirrors ----------------
__device__ __half h_x   [Bn*Tn*Cn];
__device__ __half h_q   [Bn*Tn*Cn];
__device__ __half h_hb  [Bn*Tn*HIDn];
__device__ __half h_pool[Bn*Mn*Cn];
__device__ __half h_hln [Bn*TAn*Cn];
__device__ __half h_qkv [Bn*TAn*3*Cn];
__device__ __half h_att [(long long)Bn*Hn*TAn*KPAD];
__device__ __half h_vt  [Bn*Hn*64*KPAD];
__device__ __half h_y   [Bn*TAn*Cn];
__device__ __half h_fc  [Bn*TAn*4*Cn];
__device__ __half h_out [Bn*Tn*Cn];
__device__ __half h_keyf[Bn*Tn*Cn];
__device__ __half h_keyt[Bn*Cn*Tn];
__device__ __half h_hh  [Bn*Tn*HIDn];
__device__ __half h_hht [Bn*HIDn*Tn];
__device__ __half h_dpr [Bn*Tn*Cn];
__device__ __half h_dprt[Bn*Cn*Tn];
__device__ __half h_dhh [Bn*Tn*HIDn];
__device__ __half h_dhht[Bn*HIDn*Tn];
// weight mirrors
__device__ __half h_wq  [Cn*Cn];
__device__ __half h_wk  [Cn*Cn];
__device__ __half h_wv  [Cn*Cn];
__device__ __half h_wo  [Cn*Cn];
__device__ __half h_wat [3*Cn*Cn];
__device__ __half h_wpr [Cn*Cn];
__device__ __half h_wfc [4*Cn*Cn];
__device__ __half h_wml [Cn*4*Cn];
__device__ __half h_wm0 [Bn*HIDn*Cn];
__device__ __half h_wm1 [Bn*Cn*HIDn];
__device__ __half h_wm1t[Bn*HIDn*Cn];

// ---------------- GEMM params ----------------
// A: half [M][lda] k-contig. B: half [N][ldb] k-contig. K multiple of 32.
struct GP {
    const __half* A; const __half* Bm; float* O; float* O2; __half* Oh;
    const float* bias; const float* aux; const float* aux2;
    int M, N, K, binner;
    long long lda, ldb, bA, bA2, bB, bB2;
    long long sOm, bO, bO2, bBias;
    int mode, prefix, tri;
    float scale, gscale;
};
// modes: 0 bias | 1 silu(+pre->O2) | 2 gelu | 3 attn scale+mask | 4 residual
//        5 dpred-unscaled | 6 silu-bwd(aux=pre) | 7 momentum (v*gscale)
// tri: 1 skip masked blocks, 2 cap K at m0+128

__device__ __forceinline__ void mma_f16(float* c, const unsigned* a, const unsigned* b) {
    asm volatile(
        "mma.sync.aligned.m16n8k16.row.col.f32.f16.f16.f32 "
        "{%0,%1,%2,%3}, {%4,%5,%6,%7}, {%8,%9}, {%0,%1,%2,%3};\n"
        : "+f"(c[0]), "+f"(c[1]), "+f"(c[2]), "+f"(c[3])
        : "r"(a[0]), "r"(a[1]), "r"(a[2]), "r"(a[3]), "r"(b[0]), "r"(b[1]));
}

__device__ __forceinline__ void cp16h(__half* dst, const __half* src, bool pred) {
    unsigned d = (unsigned)__cvta_generic_to_shared(dst);
    int sz = pred ? 16 : 0;
    asm volatile("cp.async.cg.shared.global [%0], [%1], 16, %2;\n"
                 :: "r"(d), "l"(src), "r"(sz));
}
#define CP_COMMIT() asm volatile("cp.async.commit_group;\n" ::)

__device__ __forceinline__ void epi_write(const GP& p, int m, int n, float v,
                                          long long offO, long long offBias) {
    if (m >= p.M || n >= p.N) return;
    long long o = offO + (long long)m * p.sOm + n;
    float bsv = p.bias ? p.bias[offBias + n] : 0.f;
    float outv = 0.f;
    switch (p.mode) {
        case 0: outv = v + bsv; break;
        case 1: { float z = v + bsv; if (p.O2) p.O2[o] = z;
                  float sg = 1.f / (1.f + __expf(-z)); outv = z * sg; } break;
        case 2: { float z = v + bsv; outv = 0.5f * z * (1.f + erff(z * 0.70710678118f)); } break;
        case 3: { float z = v * p.scale; if (m >= p.prefix && n > m) z = -1e30f;
                  outv = z; } break;
        case 4: outv = p.aux[o] + v + bsv; break;
        case 5: outv = v + bsv - p.aux[o]; break;
        case 6: { float z = p.aux[o]; float sg = 1.f / (1.f + __expf(-z));
                  outv = v * sg * (1.f + z * (1.f - sg)); } break;
        case 7: { float g = v * p.gscale; float nm = 0.9f * p.aux2[o] + g;
                  p.O2[o] = nm; outv = 0.999f * p.aux[o] - 0.01f * nm; } break;
    }
    if (p.O)  p.O[o]  = outv;
    if (p.Oh) p.Oh[o] = __float2half(outv);
}

// ---- fp16 tensor-core GEMM: 128x128 block, k-tile 32, 8 warps, 2-stage cp.async ----
// smem row layout [128][40] halves (stride 40 -> conflict-free b32 fragment LDS)
__global__ void __launch_bounds__(256, 2) gemm_h(GP p) {
    __shared__ __half sA[2][128 * 40];
    __shared__ __half sB[2][128 * 40];
    int bz = blockIdx.z;
    int bo = bz / p.binner, bi = bz % p.binner;
    const __half* Ap = p.A  + (long long)bo * p.bA + (long long)bi * p.bA2;
    const __half* Bp = p.Bm + (long long)bo * p.bB + (long long)bi * p.bB2;
    int m0 = blockIdx.y * 128, n0 = blockIdx.x * 128;

    if (p.tri == 1 && m0 > 0 && n0 >= m0 + 128) return;
    int Keff = p.K;
    if (p.tri == 2 && m0 > 0 && m0 + 128 < Keff) Keff = m0 + 128;  // mult of 128

    int tid = threadIdx.x;
    int warp = tid >> 5, lane = tid & 31;
    int wm = warp & 1, wn = warp >> 1;      // warp tile 64(m) x 32(n)
    int lq = lane >> 2, lr = lane & 3;

    float acc[4][4][4];
#pragma unroll
    for (int i = 0; i < 4; i++)
#pragma unroll
        for (int j = 0; j < 4; j++)
#pragma unroll
            for (int r = 0; r < 4; r++) acc[i][j][r] = 0.f;

    auto issue = [&](int k0, int stg) {
#pragma unroll
        for (int i = 0; i < 2; i++) {
            int chunk = tid + i * 256;          // 512 chunks per operand
            int row = chunk >> 2, c4 = chunk & 3;
            int k = k0 + c4 * 8;
            int gm = m0 + row;
            bool okA = (gm < p.M);
            cp16h(&sA[stg][row * 40 + c4 * 8],
                  okA ? (Ap + (long long)gm * p.lda + k) : Ap, okA);
            int gn = n0 + row;
            bool okB = (gn < p.N);
            cp16h(&sB[stg][row * 40 + c4 * 8],
                  okB ? (Bp + (long long)gn * p.ldb + k) : Bp, okB);
        }
    };

    int nk = Keff >> 5;                      // K multiple of 32 (mirrors padded)
    issue(0, 0);
    CP_COMMIT();

    for (int kt = 0; kt < nk; kt++) {
        int buf = kt & 1;
        asm volatile("cp.async.wait_group 0;\n" ::);
        __syncthreads();
        if (kt + 1 < nk) { issue((kt + 1) << 5, buf ^ 1); CP_COMMIT(); }

        const __half* Ab = sA[buf];
        const __half* Bb = sB[buf];
#pragma unroll
        for (int s = 0; s < 2; s++) {
            int ks = s * 16;
            unsigned af[4][4], bf[4][2];
#pragma unroll
            for (int mf = 0; mf < 4; mf++) {
                int cm = wm * 64 + mf * 16 + lq;
                af[mf][0] = *(const unsigned*)&Ab[cm * 40 + ks + 2 * lr];
                af[mf][1] = *(const unsigned*)&Ab[(cm + 8) * 40 + ks + 2 * lr];
                af[mf][2] = *(const unsigned*)&Ab[cm * 40 + ks + 8 + 2 * lr];
                af[mf][3] = *(const unsigned*)&Ab[(cm + 8) * 40 + ks + 8 + 2 * lr];
            }
#pragma unroll
            for (int nf = 0; nf < 4; nf++) {
                int cn = wn * 32 + nf * 8 + lq;
                bf[nf][0] = *(const unsigned*)&Bb[cn * 40 + ks + 2 * lr];
                bf[nf][1] = *(const unsigned*)&Bb[cn * 40 + ks + 8 + 2 * lr];
            }
#pragma unroll
            for (int mf = 0; mf < 4; mf++)
#pragma unroll
                for (int nf = 0; nf < 4; nf++)
                    mma_f16(acc[mf][nf], af[mf], bf[nf]);
        }
    }

    long long offO = (long long)bo * p.bO + (long long)bi * p.bO2;
    long long offBias = p.bBias * bz;
#pragma unroll
    for (int mf = 0; mf < 4; mf++) {
        int row = m0 + wm * 64 + mf * 16 + lq;
#pragma unroll
        for (int nf = 0; nf < 4; nf++) {
            int col = n0 + wn * 32 + nf * 8 + lr * 2;
            epi_write(p, row,     col,     acc[mf][nf][0], offO, offBias);
            epi_write(p, row,     col + 1, acc[mf][nf][1], offO, offBias);
            epi_write(p, row + 8, col,     acc[mf][nf][2], offO, offBias);
            epi_write(p, row + 8, col + 1, acc[mf][nf][3], offO, offBias);
        }
    }
}

// ---------------- fused input converts (x + all weights) ----------------
__global__ void convall_k(const float* x, const float* qw, const float* kw,
                          const float* vw, const float* ow, const float* atw,
                          const float* prw, const float* fcw, const float* mlw,
                          const float* m0, const float* m1) {
    const long long SX = (long long)Bn * Tn * Cn;          // 6291456
    const long long SW = (long long)Cn * Cn;               // 589824
    const long long SAT = 3 * SW, SFC = 4 * SW, SML = 4 * SW;
    const long long SM0 = (long long)Bn * HIDn * Cn;       // 9437184
    const long long SM1 = SM0;
    long long i = (long long)blockIdx.x * 256 + threadIdx.x;
    if (i < SX) { h_x[i] = __float2half(x[i]); return; }           i -= SX;
    if (i < SW) { h_wq[i] = __float2half(qw[i]); return; }         i -= SW;
    if (i < SW) { h_wk[i] = __float2half(kw[i]); return; }         i -= SW;
    if (i < SW) { h_wv[i] = __float2half(vw[i]); return; }         i -= SW;
    if (i < SW) { h_wo[i] = __float2half(ow[i]); return; }         i -= SW;
    if (i < SAT){ h_wat[i] = __float2half(atw[i]); return; }       i -= SAT;
    if (i < SW) { h_wpr[i] = __float2half(prw[i]); return; }       i -= SW;
    if (i < SFC){ h_wfc[i] = __float2half(fcw[i]); return; }       i -= SFC;
    if (i < SML){ h_wml[i] = __float2half(mlw[i]); return; }       i -= SML;
    if (i < SM0){ h_wm0[i] = __float2half(m0[i]); return; }        i -= SM0;
    if (i < SM1){ h_wm1[i] = __float2half(m1[i]); return; }
}
#define CONVALL_TOTAL (6291456LL + 5*589824LL + 1769472LL + 2*2359296LL + 2*9437184LL)

// batched tiled transpose+convert: in [z][R][Cc] fp32 -> out [z][Cc][R] fp16
__global__ void tconv_k(const float* in, __half* out, int R, int Cc) {
    __shared__ float tile[32][33];
    long long zo = (long long)blockIdx.z * R * Cc;
    int x = blockIdx.x * 32 + threadIdx.x;
#pragma unroll
    for (int j = threadIdx.y; j < 32; j += 8) {
        int y = blockIdx.y * 32 + j;
        if (x < Cc && y < R) tile[j][threadIdx.x] = in[zo + (long long)y * Cc + x];
    }
    __syncthreads();
    int ox = blockIdx.y * 32 + threadIdx.x;
#pragma unroll
    for (int j = threadIdx.y; j < 32; j += 8) {
        int oy = blockIdx.x * 32 + j;
        if (ox < R && oy < Cc) out[zo + (long long)oy * R + ox] = __float2half(tile[threadIdx.x][j]);
    }
}

// batched tiled fp16 transpose: in [z][R][Cc] -> out [z][Cc][R]
__global__ void tconvh_k(const __half* in, __half* out, int R, int Cc) {
    __shared__ __half tile[32][34];
    long long zo = (long long)blockIdx.z * R * Cc;
    int x = blockIdx.x * 32 + threadIdx.x;
#pragma unroll
    for (int j = threadIdx.y; j < 32; j += 8) {
        int y = blockIdx.y * 32 + j;
        if (x < Cc && y < R) tile[j][threadIdx.x] = in[zo + (long long)y * Cc + x];
    }
    __syncthreads();
    int ox = blockIdx.y * 32 + threadIdx.x;
#pragma unroll
    for (int j = threadIdx.y; j < 32; j += 8) {
        int oy = blockIdx.x * 32 + j;
        if (ox < R && oy < Cc) out[zo + (long long)oy * R + ox] = tile[threadIdx.x][j];
    }
}

// V transpose from fp16 QKVH: per (b,h): in rows t (stride 3C, V slice d=0..63)
// -> out [64][KPAD], zero-pad t >= TAn.   grid: (KPAD/32, 2, Bn*Hn), block (32,8)
__global__ void vt2_k(const __half* qkvh, __half* vt) {
    __shared__ __half tile[32][34];
    int bh = blockIdx.z;
    int b = bh / Hn, h = bh % Hn;
    const __half* src = qkvh + (long long)b * TAn * 3 * Cn + 2 * Cn + h * 64;
    int t0 = blockIdx.x * 32, d0 = blockIdx.y * 32;
#pragma unroll
    for (int j = threadIdx.y; j < 32; j += 8) {
        int t = t0 + j;
        tile[j][threadIdx.x] = (t < TAn) ? src[(long long)t * 3 * Cn + d0 + threadIdx.x]
                                         : __half(0.f);
    }
    __syncthreads();
    __half* dst = vt + (long long)bh * 64 * KPAD;
#pragma unroll
    for (int j = threadIdx.y; j < 32; j += 8) {
        int d = d0 + j;
        dst[(long long)d * KPAD + t0 + threadIdx.x] = tile[threadIdx.x][j];
    }
}

// ---------------- elementwise ----------------
__global__ void pool_k(const float* mem, float* pool, __half* poolh) {
    int i = blockIdx.x * 256 + threadIdx.x;
    if (i >= Bn * Mn * Cn) return;
    int c = i % Cn;
    int r = i / Cn;
    int m = r % Mn;
    int b = r / Mn;
    const float* pp = mem + ((long long)b * Tn + m * (Tn / Mn)) * Cn + c;
    float s = 0.f;
#pragma unroll 8
    for (int j = 0; j < Tn / Mn; j++) s += pp[(long long)j * Cn];
    float v = s * (1.f / (Tn / Mn));
    pool[i] = v;
    poolh[i] = __float2half(v);
}

__global__ void build_xa_k(const float* retr, const float* persist, const float* x, float* xa) {
    long long i = (long long)blockIdx.x * 256 + threadIdx.x;
    if (i >= (long long)Bn * TAn * Cn) return;
    int c = (int)(i % Cn);
    long long r = i / Cn;
    int t = (int)(r % TAn);
    int b = (int)(r / TAn);
    float v;
    if (t < Mn)        v = retr[((long long)b * Mn + t) * Cn + c];
    else if (t < PREn) v = persist[(long long)(t - Mn) * Cn + c];
    else               v = x[((long long)b * Tn + (t - PREn)) * Cn + c];
    xa[i] = v;
}

__global__ void ln_k(const float* x, __half* o, const float* w, const float* bb) {
    long long row = blockIdx.x;
    const float* xr = x + row * Cn;
    __half* orow = o + row * Cn;
    int t = threadIdx.x;
    __shared__ float s1[256], s2[256];
    float v0 = xr[t], v1 = xr[t + 256], v2 = xr[t + 512];
    s1[t] = v0 + v1 + v2;
    s2[t] = v0 * v0 + v1 * v1 + v2 * v2;
    __syncthreads();
    for (int st = 128; st > 0; st >>= 1) {
        if (t < st) { s1[t] += s1[t + st]; s2[t] += s2[t + st]; }
        __syncthreads();
    }
    float mean = s1[0] * (1.f / Cn);
    float var  = s2[0] * (1.f / Cn) - mean * mean;
    float rs = rsqrtf(var + 1e-5f);
    orow[t]       = __float2half((v0 - mean) * rs * w[t]       + bb[t]);
    orow[t + 256] = __float2half((v1 - mean) * rs * w[t + 256] + bb[t + 256]);
    orow[t + 512] = __float2half((v2 - mean) * rs * w[t + 512] + bb[t + 512]);
}

// softmax in-place on fp16 scores (fp32 math; exp recomputed — row lives in L1).
__global__ void softmax_k(__half* ah) {
    long long row = blockIdx.x;
    int m = (int)(row % TAn);
    __half* rh = ah + row * KPAD;
    int lim = (m < PREn) ? TAn : (m + 1);
    int t = threadIdx.x;
    __shared__ float red[256];
    float mx = -1e30f;
    for (int c = t; c < lim; c += 256) mx = fmaxf(mx, __half2float(rh[c]));
    red[t] = mx; __syncthreads();
    for (int st = 128; st > 0; st >>= 1) { if (t < st) red[t] = fmaxf(red[t], red[t + st]); __syncthreads(); }
    mx = red[0]; __syncthreads();
    float s = 0.f;
    for (int c = t; c < lim; c += 256) s += __expf(__half2float(rh[c]) - mx);
    red[t] = s; __syncthreads();
    for (int st = 128; st > 0; st >>= 1) { if (t < st) red[t] += red[t + st]; __syncthreads(); }
    float inv = 1.f / red[0];
    for (int c = t; c < lim; c += 256)
        rh[c] = __float2half(__expf(__half2float(rh[c]) - mx) * inv);
    for (int c = lim + t; c < KPAD; c += 256) rh[c] = __half(0.f);
}

__global__ void copyout_k(const float* xa, float* dout, __half* outh) {
    long long i = (long long)blockIdx.x * 256 + threadIdx.x;
    if (i >= (long long)Bn * Tn * Cn) return;
    int c = (int)(i % Cn);
    long long r = i / Cn;
    int t = (int)(r % Tn);
    int b = (int)(r / Tn);
    float v = xa[((long long)b * TAn + PREn + t) * Cn + c];
    dout[i] = v;
    outh[i] = __float2half(v);
}

__global__ void colsum_part_k(const float* src, float* part, int cols) {
    int i = blockIdx.x * 256 + threadIdx.x;
    int total = SLICES * Bn * cols;
    if (i >= total) return;
    int s = i / (Bn * cols);
    int rem = i % (Bn * cols);
    int b = rem / cols, c = rem % cols;
    const float* p = src + ((long long)b * Tn + s * (Tn / SLICES)) * cols + c;
    float g = 0.f;
    for (int r = 0; r < Tn / SLICES; r++) g += p[(long long)r * cols];
    part[i] = g;
}

__global__ void colsum_fin_k(const float* part, const float* memb, const float* mom,
                             float* nb, float* nm, int n, float gs) {
    int i = blockIdx.x * 256 + threadIdx.x;
    if (i >= n) return;
    float g = 0.f;
    for (int s = 0; s < SLICES; s++) g += part[(long long)s * n + i];
    float m2 = 0.9f * mom[i] + g * gs;
    nm[i] = m2;
    nb[i] = 0.999f * memb[i] - 0.01f * m2;
}

// ---------------- host ----------------
static void run_gemm(const __half* A, long long lda, long long bA, long long bA2,
                     const __half* Bm, long long ldb, long long bB, long long bB2,
                     float* O, long long sOm, long long bO, long long bO2,
                     int M, int N, int K, int batch, int binner,
                     const float* bias, long long bBias, int mode,
                     float* O2, __half* Oh, const float* aux, const float* aux2,
                     float scale, float gscale, int tri)
{
    GP p;
    p.A = A; p.Bm = Bm; p.O = O; p.O2 = O2; p.Oh = Oh;
    p.bias = bias; p.aux = aux; p.aux2 = aux2;
    p.M = M; p.N = N; p.K = K; p.binner = binner;
    p.lda = lda; p.ldb = ldb; p.bA = bA; p.bA2 = bA2; p.bB = bB; p.bB2 = bB2;
    p.sOm = sOm; p.bO = bO; p.bO2 = bO2; p.bBias = bBias;
    p.mode = mode; p.prefix = PREn; p.tri = tri; p.scale = scale; p.gscale = gscale;
    dim3 g((N + 127) / 128, (M + 127) / 128, batch);
    gemm_h<<<g, 256>>>(p);
}

static void tconv(const float* in, __half* out, int R, int Cc, int batch) {
    dim3 g((Cc + 31) / 32, (R + 31) / 32, batch);
    tconv_k<<<g, dim3(32, 8)>>>(in, out, R, Cc);
}
static void tconvh(const __half* in, __half* out, int R, int Cc, int batch) {
    dim3 g((Cc + 31) / 32, (R + 31) / 32, batch);
    tconvh_k<<<g, dim3(32, 8)>>>(in, out, R, Cc);
}

extern "C" void kernel_launch(void* const* d_in, const int* in_sizes, int n_in,
                              void* d_out, int out_size) {
    const float* x           = (const float*)d_in[0];
    const float* persist     = (const float*)d_in[1];
    const float* ln1_w       = (const float*)d_in[2];
    const float* ln1_b       = (const float*)d_in[3];
    const float* ln2_w       = (const float*)d_in[4];
    const float* ln2_b       = (const float*)d_in[5];
    const float* attn_w      = (const float*)d_in[6];
    const float* attn_b      = (const float*)d_in[7];
    const float* attn_proj_w = (const float*)d_in[8];
    const float* attn_proj_b = (const float*)d_in[9];
    const float* fc_w        = (const float*)d_in[10];
    const float* fc_b        = (const float*)d_in[11];
    const float* mlp_proj_w  = (const float*)d_in[12];
    const float* mlp_proj_b  = (const float*)d_in[13];
    const float* q_w         = (const float*)d_in[14];
    const float* q_b         = (const float*)d_in[15];
    const float* k_w         = (const float*)d_in[16];
    const float* k_b         = (const float*)d_in[17];
    const float* v_w         = (const float*)d_in[18];
    const float* v_b         = (const float*)d_in[19];
    const float* o_w         = (const float*)d_in[20];
    const float* o_b         = (const float*)d_in[21];
    const float* mem_w0      = (const float*)d_in[22];
    const float* mem_b0      = (const float*)d_in[23];
    const float* mem_w1      = (const float*)d_in[24];
    const float* mem_b1      = (const float*)d_in[25];
    const float* mom_w0      = (const float*)d_in[26];
    const float* mom_b0      = (const float*)d_in[27];
    const float* mom_w1      = (const float*)d_in[28];
    const float* mom_b1      = (const float*)d_in[29];
    float* out = (float*)d_out;

    float *MEM, *POOL, *RETR, *XA, *VAL, *PRE, *DPR, *DHH, *P0, *P1;
    cudaGetSymbolAddress((void**)&MEM, g_mem);
    cudaGetSymbolAddress((void**)&POOL, g_pool);
    cudaGetSymbolAddress((void**)&RETR, g_retr);
    cudaGetSymbolAddress((void**)&XA, g_xa);
    cudaGetSymbolAddress((void**)&VAL, g_val);
    cudaGetSymbolAddress((void**)&PRE, g_pre);
    cudaGetSymbolAddress((void**)&DPR, g_dpr);
    cudaGetSymbolAddress((void**)&DHH, g_dhh);
    cudaGetSymbolAddress((void**)&P0, g_p0);
    cudaGetSymbolAddress((void**)&P1, g_p1);
    __half *XH, *QH, *HBH, *POOLH, *HLNH, *QKVH, *ATTH, *VTH, *YH, *FCH, *OUTH,
           *KEYH, *KEYT, *HHH, *HHT, *DPRH, *DPRT, *DHHH, *DHHT,
           *WQ, *WK, *WV, *WO, *WAT, *WPR, *WFC, *WML, *WM0, *WM1, *WM1T;
    cudaGetSymbolAddress((void**)&XH, h_x);
    cudaGetSymbolAddress((void**)&QH, h_q);
    cudaGetSymbolAddress((void**)&HBH, h_hb);
    cudaGetSymbolAddress((void**)&POOLH, h_pool);
    cudaGetSymbolAddress((void**)&HLNH, h_hln);
    cudaGetSymbolAddress((void**)&QKVH, h_qkv);
    cudaGetSymbolAddress((void**)&ATTH, h_att);
    cudaGetSymbolAddress((void**)&VTH, h_vt);
    cudaGetSymbolAddress((void**)&YH, h_y);
    cudaGetSymbolAddress((void**)&FCH, h_fc);
    cudaGetSymbolAddress((void**)&OUTH, h_out);
    cudaGetSymbolAddress((void**)&KEYH, h_keyf);
    cudaGetSymbolAddress((void**)&KEYT, h_keyt);
    cudaGetSymbolAddress((void**)&HHH, h_hh);
    cudaGetSymbolAddress((void**)&HHT, h_hht);
    cudaGetSymbolAddress((void**)&DPRH, h_dpr);
    cudaGetSymbolAddress((void**)&DPRT, h_dprt);
    cudaGetSymbolAddress((void**)&DHHH, h_dhh);
    cudaGetSymbolAddress((void**)&DHHT, h_dhht);
    cudaGetSymbolAddress((void**)&WQ, h_wq);
    cudaGetSymbolAddress((void**)&WK, h_wk);
    cudaGetSymbolAddress((void**)&WV, h_wv);
    cudaGetSymbolAddress((void**)&WO, h_wo);
    cudaGetSymbolAddress((void**)&WAT, h_wat);
    cudaGetSymbolAddress((void**)&WPR, h_wpr);
    cudaGetSymbolAddress((void**)&WFC, h_wfc);
    cudaGetSymbolAddress((void**)&WML, h_wml);
    cudaGetSymbolAddress((void**)&WM0, h_wm0);
    cudaGetSymbolAddress((void**)&WM1, h_wm1);
    cudaGetSymbolAddress((void**)&WM1T, h_wm1t);

    const long long TC  = (long long)Tn * Cn;
    const long long TH  = (long long)Tn * HIDn;
    const long long CH  = (long long)Cn * HIDn;
    const long long HC  = (long long)HIDn * Cn;
    const long long TAC = (long long)TAn * Cn;
    const float GS = 2.f / (float)(Tn * Cn);

    const long long o_nw0  = 6291456LL;
    const long long o_nb0  = 15728640LL;
    const long long o_nw1  = 15740928LL;
    const long long o_nb1  = 25178112LL;
    const long long o_nmw0 = 25184256LL;
    const long long o_nmb0 = 34621440LL;
    const long long o_nmw1 = 34633728LL;
    const long long o_nmb1 = 44070912LL;

    // fused converts (x + all weights), plus w1 transpose
    convall_k<<<(int)((CONVALL_TOTAL + 255) / 256), 256>>>(
        x, q_w, k_w, v_w, o_w, attn_w, attn_proj_w, fc_w, mlp_proj_w, mem_w0, mem_w1);
    tconv(mem_w1, WM1T, Cn, HIDn, Bn);

    // 1. q = x @ q_w^T + q_b      (fp16-only out)
    run_gemm(XH, Cn, 0, 0,  WQ, Cn, 0, 0,  nullptr, Cn, 0, 0,
             Bn * Tn, Cn, Cn, 1, 1, q_b, 0, 0, nullptr, QH, nullptr, nullptr, 0.f, 0.f, 0);
    // 2. h = silu(q @ w0^T + b0)  (fp16-only out)
    run_gemm(QH, Cn, TC, 0,  WM0, Cn, HC, 0,  nullptr, HIDn, TH, 0,
             Tn, HIDn, Cn, Bn, 1, mem_b0, HIDn, 1, nullptr, HBH, nullptr, nullptr, 0.f, 0.f, 0);
    // 3. mem = h @ w1^T + b1      (fp32 for pool)
    run_gemm(HBH, HIDn, TH, 0,  WM1, HIDn, CH, 0,  MEM, Cn, TC, 0,
             Tn, Cn, HIDn, Bn, 1, mem_b1, Cn, 0, nullptr, nullptr, nullptr, nullptr, 0.f, 0.f, 0);
    pool_k<<<(Bn * Mn * Cn + 255) / 256, 256>>>(MEM, POOL, POOLH);
    run_gemm(POOLH, Cn, 0, 0,  WO, Cn, 0, 0,  RETR, Cn, 0, 0,
             Bn * Mn, Cn, Cn, 1, 1, o_b, 0, 0, nullptr, nullptr, nullptr, nullptr, 0.f, 0.f, 0);
    build_xa_k<<<(int)(((long long)Bn * TAn * Cn + 255) / 256), 256>>>(RETR, persist, x, XA);
    ln_k<<<Bn * TAn, 256>>>(XA, HLNH, ln1_w, ln1_b);
    // qkv (fp16-only out)
    run_gemm(HLNH, Cn, 0, 0,  WAT, Cn, 0, 0,  nullptr, 3 * Cn, 0, 0,
             Bn * TAn, 3 * Cn, Cn, 1, 1, attn_b, 0, 0, nullptr, QKVH, nullptr, nullptr, 0.f, 0.f, 0);
    vt2_k<<<dim3(KPAD / 32, 2, Bn * Hn), dim3(32, 8)>>>(QKVH, VTH);
    // scores -> fp16 ATTH direct
    run_gemm(QKVH, 3 * Cn, (long long)TAn * 3 * Cn, 64,
             QKVH + Cn, 3 * Cn, (long long)TAn * 3 * Cn, 64,
             nullptr, KPAD, (long long)Hn * TAn * KPAD, (long long)TAn * KPAD,
             TAn, TAn, 64, Bn * Hn, Hn, nullptr, 0, 3,
             nullptr, ATTH, nullptr, nullptr, 0.125f, 0.f, 1);
    softmax_k<<<Bn * Hn * TAn, 256>>>(ATTH);
    // y = att @ V (fp16-only out)
    run_gemm(ATTH, KPAD, (long long)Hn * TAn * KPAD, (long long)TAn * KPAD,
             VTH, KPAD, (long long)Hn * 64 * KPAD, (long long)64 * KPAD,
             nullptr, Cn, TAC, 64,
             TAn, 64, KPAD, Bn * Hn, Hn, nullptr, 0, 0,
             nullptr, YH, nullptr, nullptr, 0.f, 0.f, 2);
    // attn proj + residual (fp32 XA)
    run_gemm(YH, Cn, 0, 0,  WPR, Cn, 0, 0,  XA, Cn, 0, 0,
             Bn * TAn, Cn, Cn, 1, 1, attn_proj_b, 0, 4, nullptr, nullptr, XA, nullptr, 0.f, 0.f, 0);
    ln_k<<<Bn * TAn, 256>>>(XA, HLNH, ln2_w, ln2_b);
    // fc gelu (fp16-only out)
    run_gemm(HLNH, Cn, 0, 0,  WFC, Cn, 0, 0,  nullptr, 4 * Cn, 0, 0,
             Bn * TAn, 4 * Cn, Cn, 1, 1, fc_b, 0, 2, nullptr, FCH, nullptr, nullptr, 0.f, 0.f, 0);
    // mlp proj + residual
    run_gemm(FCH, 4 * Cn, 0, 0,  WML, 4 * Cn, 0, 0,  XA, Cn, 0, 0,
             Bn * TAn, Cn, 4 * Cn, 1, 1, mlp_proj_b, 0, 4, nullptr, nullptr, XA, nullptr, 0.f, 0.f, 0);
    copyout_k<<<(int)(((long long)Bn * TC + 255) / 256), 256>>>(XA, out, OUTH);
    // keys (fp16-only) / vals (fp32 aux)
    run_gemm(OUTH, Cn, 0, 0,  WK, Cn, 0, 0,  nullptr, Cn, 0, 0,
             Bn * Tn, Cn, Cn, 1, 1, k_b, 0, 0, nullptr, KEYH, nullptr, nullptr, 0.f, 0.f, 0);
    run_gemm(OUTH, Cn, 0, 0,  WV, Cn, 0, 0,  VAL, Cn, 0, 0,
             Bn * Tn, Cn, Cn, 1, 1, v_b, 0, 0, nullptr, nullptr, nullptr, nullptr, 0.f, 0.f, 0);
    tconvh(KEYH, KEYT, Tn, Cn, Bn);
    // pre/hh (PRE fp32 aux, HH fp16)
    run_gemm(KEYH, Cn, TC, 0,  WM0, Cn, HC, 0,  nullptr, HIDn, TH, 0,
             Tn, HIDn, Cn, Bn, 1, mem_b0, HIDn, 1, PRE, HHH, nullptr, nullptr, 0.f, 0.f, 0);
    tconvh(HHH, HHT, Tn, HIDn, Bn);
    // dpred (unscaled; fp32 for colsum + fp16 mirror)
    run_gemm(HHH, HIDn, TH, 0,  WM1, HIDn, CH, 0,  DPR, Cn, TC, 0,
             Tn, Cn, HIDn, Bn, 1, mem_b1, Cn, 5, nullptr, DPRH, VAL, nullptr, 0.f, 0.f, 0);
    tconvh(DPRH, DPRT, Tn, Cn, Bn);
    // g_w1 + update
    run_gemm(DPRT, Tn, (long long)Cn * Tn, 0,  HHT, Tn, (long long)HIDn * Tn, 0,
             out + o_nw1, HIDn, CH, 0,
             Cn, HIDn, Tn, Bn, 1, nullptr, 0, 7,
             out + o_nmw1, nullptr, mem_w1, mom_w1, 0.f, GS, 0);
    // dh (unscaled; fp32 for colsum + fp16 mirror)
    run_gemm(DPRH, Cn, TC, 0,  WM1T, Cn, HC, 0,  DHH, HIDn, TH, 0,
             Tn, HIDn, Cn, Bn, 1, nullptr, 0, 6, nullptr, DHHH, PRE, nullptr, 0.f, 0.f, 0);
    tconvh(DHHH, DHHT, Tn, HIDn, Bn);
    // g_w0 + update
    run_gemm(DHHT, Tn, (long long)HIDn * Tn, 0,  KEYT, Tn, (long long)Cn * Tn, 0,
             out + o_nw0, Cn, HC, 0,
             HIDn, Cn, Tn, Bn, 1, nullptr, 0, 7,
             out + o_nmw0, nullptr, mem_w0, mom_w0, 0.f, GS, 0);
    // bias grads
    colsum_part_k<<<(SLICES * Bn * Cn + 255) / 256, 256>>>(DPR, P1, Cn);
    colsum_fin_k<<<(Bn * Cn + 255) / 256, 256>>>(P1, mem_b1, mom_b1,
                                                 out + o_nb1, out + o_nmb1, Bn * Cn, GS);
    colsum_part_k<<<(SLICES * Bn * HIDn + 255) / 256, 256>>>(DHH, P0, HIDn);
    colsum_fin_k<<<(Bn * HIDn + 255) / 256, 256>>>(P0, mem_b0, mom_b0,
                                                   out + o_nb0, out + o_nmb0, Bn * HIDn, GS);
    (void)in_sizes; (void)n_in; (void)out_size;
}